// round 17
// baseline (speedup 1.0000x reference)
#include <cuda_runtime.h>
#include <cuda_fp16.h>
#include <cstdint>
#include <math.h>

#define NOBS   65536
#define DIM    64
#define NELEM  (NOBS * DIM)

// ---------------------------------------------------------------------------
// Weight fragments (fp16), mma.sync.m16n8k16 B-fragment order.
// Step-path weights: uint2 = {b0_hi, b1_hi} (single-pass, unpaired — low regs).
// W1 X0-half: uint4 = {b0_hi, b1_hi, b0_lo, b1_lo} (3-pass, P0 prep only).
// entry (nj*KT + ki)*32 + lane.
// ---------------------------------------------------------------------------
__device__ uint2 g_w1af[128 * 32];  // 32 nj x 4 ki  (X part of W1)
__device__ uint4 g_w1bf[128 * 32];  // 32 nj x 4 ki  (X0 part, used once)
__device__ uint2 g_w2f[512 * 32];   // 32 nj x 16 ki
__device__ uint2 g_w3f[128 * 32];   //  8 nj x 16 ki

// Step-invariant partial: P0 = X0 @ W1[64:128] + b1   [65536 x 256] f32
__device__ float g_p0[(size_t)NOBS * 256];

// ---------------------------------------------------------------------------
// threefry2x32 (JAX partitionable, exact)
// ---------------------------------------------------------------------------
__host__ __device__ __forceinline__ void tf2x32(uint32_t k0, uint32_t k1,
                                                uint32_t& x0, uint32_t& x1) {
  uint32_t ks2 = k0 ^ k1 ^ 0x1BD11BDAu;
  x0 += k0; x1 += k1;
#define TFR(r) { x0 += x1; x1 = (x1 << (r)) | (x1 >> (32 - (r))); x1 ^= x0; }
  TFR(13) TFR(15) TFR(26) TFR(6)
  x0 += k1;  x1 += ks2 + 1u;
  TFR(17) TFR(29) TFR(16) TFR(24)
  x0 += ks2; x1 += k0 + 2u;
  TFR(13) TFR(15) TFR(26) TFR(6)
  x0 += k0;  x1 += k1 + 3u;
  TFR(17) TFR(29) TFR(16) TFR(24)
  x0 += k1;  x1 += ks2 + 4u;
  TFR(13) TFR(15) TFR(26) TFR(6)
  x0 += ks2; x1 += k0 + 5u;
#undef TFR
}

__device__ __forceinline__ void dev_split2(uint32_t k0, uint32_t k1,
                                           uint32_t out[2][2]) {
#pragma unroll
  for (uint32_t j = 0; j < 2; j++) {
    uint32_t a = 0u, b = j;
    tf2x32(k0, k1, a, b);
    out[j][0] = a; out[j][1] = b;
  }
}

__device__ __forceinline__ float erfinv_xla(float x) {
  float w = -log1pf(-x * x);
  float p;
  if (w < 5.0f) {
    w -= 2.5f;
    p = 2.81022636e-08f;
    p = fmaf(p, w, 3.43273939e-07f);
    p = fmaf(p, w, -3.5233877e-06f);
    p = fmaf(p, w, -4.39150654e-06f);
    p = fmaf(p, w, 0.00021858087f);
    p = fmaf(p, w, -0.00125372503f);
    p = fmaf(p, w, -0.00417768164f);
    p = fmaf(p, w, 0.246640727f);
    p = fmaf(p, w, 1.50140941f);
  } else {
    w = sqrtf(w) - 3.0f;
    p = -0.000200214257f;
    p = fmaf(p, w, 0.000100950558f);
    p = fmaf(p, w, 0.00134934322f);
    p = fmaf(p, w, -0.00367342844f);
    p = fmaf(p, w, 0.00573950773f);
    p = fmaf(p, w, -0.0076224613f);
    p = fmaf(p, w, 0.00943887047f);
    p = fmaf(p, w, 1.00167406f);
    p = fmaf(p, w, 2.83297682f);
  }
  return p * x;
}
__device__ __forceinline__ float bits_to_normal(uint32_t bits) {
  float f = __uint_as_float((bits >> 9) | 0x3F800000u) - 1.0f;
  const float lo = -0.99999994f;
  float u = fmaxf(lo, f * 2.0f + lo);
  return 1.41421356237f * erfinv_xla(u);
}

// ---------------------------------------------------------------------------
// fp16 helpers
// ---------------------------------------------------------------------------
__device__ __forceinline__ uint32_t pack_h2(float a, float b) {
  uint32_t la = (uint32_t)__half_as_ushort(__float2half_rn(a));
  uint32_t hb = (uint32_t)__half_as_ushort(__float2half_rn(b));
  return la | (hb << 16);
}
__device__ __forceinline__ void split_pack(float a, float b,
                                           uint32_t& hi, uint32_t& lo) {
  __half ah = __float2half_rn(a), bh = __float2half_rn(b);
  hi = (uint32_t)__half_as_ushort(ah) |
       ((uint32_t)__half_as_ushort(bh) << 16);
  lo = pack_h2(a - __half2float(ah), b - __half2float(bh));
}

__device__ __forceinline__ void mma_f16(float (&d)[4], const uint32_t (&a)[4],
                                        uint32_t b0, uint32_t b1) {
  asm volatile(
      "mma.sync.aligned.m16n8k16.row.col.f32.f16.f16.f32 "
      "{%0,%1,%2,%3}, {%4,%5,%6,%7}, {%8,%9}, {%0,%1,%2,%3};"
      : "+f"(d[0]), "+f"(d[1]), "+f"(d[2]), "+f"(d[3])
      : "r"(a[0]), "r"(a[1]), "r"(a[2]), "r"(a[3]), "r"(b0), "r"(b1));
}

// ---------------------------------------------------------------------------
// Weight prep
// ---------------------------------------------------------------------------
__global__ void prep_weights(const float* __restrict__ W1,
                             const float* __restrict__ W2,
                             const float* __restrict__ W3) {
  int tid = blockIdx.x * 256 + threadIdx.x;
  int T = tid >> 5, lane = tid & 31;
  if (T >= 896) return;
  int g = lane >> 2, t = lane & 3;
  const float* W; int ldn, ni, ki;
  if (T < 256)      { ni = (T) >> 3;       ki = T & 7;          W = W1; ldn = 256; }
  else if (T < 768) { int T2 = T - 256; ni = T2 >> 4; ki = T2 & 15; W = W2; ldn = 256; }
  else              { int T3 = T - 768; ni = T3 >> 4; ki = T3 & 15; W = W3; ldn = 64;  }
  int n  = ni * 8 + g;
  int k0 = ki * 16 + 2 * t;
  float w00 = W[(k0    ) * ldn + n], w01 = W[(k0 + 1) * ldn + n];
  float w10 = W[(k0 + 8) * ldn + n], w11 = W[(k0 + 9) * ldn + n];
  uint32_t h0, l0, h1, l1;
  split_pack(w00, w01, h0, l0);
  split_pack(w10, w11, h1, l1);
  if (T < 256) {
    if (ki < 4) g_w1af[(ni * 4 + ki) * 32 + lane] = make_uint2(h0, h1);
    else        g_w1bf[(ni * 4 + (ki - 4)) * 32 + lane] = make_uint4(h0, h1, l0, l1);
  } else if (T < 768) {
    g_w2f[(T - 256) * 32 + lane] = make_uint2(h0, h1);
  } else {
    g_w3f[(T - 768) * 32 + lane] = make_uint2(h0, h1);
  }
}

// ---------------------------------------------------------------------------
// Single-pass fragment GEMM (unpaired, low register pressure)
// ---------------------------------------------------------------------------
template<int KT, int NJ, int MT>
__device__ __forceinline__ void gemm1p(
    float (&acc)[MT][NJ][4],
    const char* __restrict__ aHi, int mBase, int lane,
    const uint2* __restrict__ B, int njBase) {
#pragma unroll
  for (int ki = 0; ki < KT; ++ki) {
    uint32_t ah[MT][4];
#pragma unroll
    for (int mt = 0; mt < MT; ++mt) {
      uint4 vh = *(const uint4*)(aHi + (((mBase + mt) * KT + ki) * 512 + lane * 16));
      ah[mt][0] = vh.x; ah[mt][1] = vh.y; ah[mt][2] = vh.z; ah[mt][3] = vh.w;
    }
#pragma unroll
    for (int jc = 0; jc < NJ; jc += 4) {
      constexpr int JW = (NJ < 4) ? NJ : 4;
      uint2 bv[JW];
#pragma unroll
      for (int j = 0; j < JW; ++j)
        bv[j] = B[((njBase + jc + j) * KT + ki) * 32 + lane];
#pragma unroll
      for (int mt = 0; mt < MT; ++mt)
#pragma unroll
        for (int j = 0; j < JW; ++j)
          mma_f16(acc[mt][jc + j], ah[mt], bv[j].x, bv[j].y);
    }
  }
}

// 3-pass variant (P0 prep only)
template<int KT, int NJ, int MT>
__device__ __forceinline__ void gemm3p(
    float (&acc)[MT][NJ][4],
    const char* __restrict__ aHi, const char* __restrict__ aLo,
    int mBase, int lane,
    const uint4* __restrict__ B, int njBase) {
#pragma unroll
  for (int ki = 0; ki < KT; ++ki) {
    uint32_t ah[MT][4], al[MT][4];
#pragma unroll
    for (int mt = 0; mt < MT; ++mt) {
      uint4 vh = *(const uint4*)(aHi + (((mBase + mt) * KT + ki) * 512 + lane * 16));
      ah[mt][0] = vh.x; ah[mt][1] = vh.y; ah[mt][2] = vh.z; ah[mt][3] = vh.w;
      uint4 vl = *(const uint4*)(aLo + (((mBase + mt) * KT + ki) * 512 + lane * 16));
      al[mt][0] = vl.x; al[mt][1] = vl.y; al[mt][2] = vl.z; al[mt][3] = vl.w;
    }
#pragma unroll
    for (int jc = 0; jc < NJ; jc += 4) {
      constexpr int JW = (NJ < 4) ? NJ : 4;
      uint4 bv[JW];
#pragma unroll
      for (int j = 0; j < JW; ++j)
        bv[j] = B[((njBase + jc + j) * KT + ki) * 32 + lane];
#pragma unroll
      for (int mt = 0; mt < MT; ++mt)
#pragma unroll
        for (int j = 0; j < JW; ++j) {
          mma_f16(acc[mt][jc + j], ah[mt], bv[j].x, bv[j].y);
          mma_f16(acc[mt][jc + j], al[mt], bv[j].x, bv[j].y);
          mma_f16(acc[mt][jc + j], ah[mt], bv[j].z, bv[j].w);
        }
    }
  }
}

// ---------------------------------------------------------------------------
// P0 prep: P0 = X0 @ W1[64:128] + b1   (3-pass fp16, one-time)
// ---------------------------------------------------------------------------
__global__ void __launch_bounds__(256)
prep_p0(const float* __restrict__ X0g, const float* __restrict__ b1) {
  extern __shared__ char sm[];
  char* actHi = sm;
  char* actLo = sm + 8192;
  const int tid = threadIdx.x;
  const int wid = tid >> 5, lane = tid & 31;
  const int g = lane >> 2, t = lane & 3;
  const int rowBase = blockIdx.x * 64;

#pragma unroll
  for (int it = 0; it < 2; ++it) {
    int tile = wid * 2 + it;
    int mi = tile >> 2, ki = tile & 3;
    int kc = ki * 16;
    const float* p0 = X0g + (size_t)(rowBase + mi * 16 + g) * DIM + kc;
    const float* p1 = p0 + 8 * DIM;
    float2 v00 = *(const float2*)(p0 + 2 * t);
    float2 v01 = *(const float2*)(p0 + 2 * t + 8);
    float2 v10 = *(const float2*)(p1 + 2 * t);
    float2 v11 = *(const float2*)(p1 + 2 * t + 8);
    uint32_t h0, l0, h1, l1, h2, l2, h3, l3;
    split_pack(v00.x, v00.y, h0, l0);
    split_pack(v10.x, v10.y, h1, l1);
    split_pack(v01.x, v01.y, h2, l2);
    split_pack(v11.x, v11.y, h3, l3);
    int off = (mi * 4 + ki) * 512 + lane * 16;
    *(uint4*)(actHi + off) = make_uint4(h0, h1, h2, h3);
    *(uint4*)(actLo + off) = make_uint4(l0, l1, l2, l3);
  }
  __syncthreads();

  const int mrow = wid >> 2, ncol = wid & 3;
  float acc[2][8][4];
#pragma unroll
  for (int a = 0; a < 2; ++a)
#pragma unroll
    for (int b = 0; b < 8; ++b)
#pragma unroll
      for (int c = 0; c < 4; ++c) acc[a][b][c] = 0.f;
  gemm3p<4, 8, 2>(acc, actHi, actLo, mrow * 2, lane, g_w1bf, ncol * 8);

#pragma unroll
  for (int j = 0; j < 8; ++j) {
    int nj = ncol * 8 + j;
    int c0 = nj * 8 + 2 * t;
    float bb0 = b1[c0], bb1 = b1[c0 + 1];
#pragma unroll
    for (int mt = 0; mt < 2; ++mt) {
      int r = rowBase + (mrow * 2 + mt) * 16 + g;
      float2 oA = make_float2(acc[mt][j][0] + bb0, acc[mt][j][1] + bb1);
      float2 oB = make_float2(acc[mt][j][2] + bb0, acc[mt][j][3] + bb1);
      *(float2*)&g_p0[(size_t)r * 256 + c0]       = oA;
      *(float2*)&g_p0[(size_t)(r + 8) * 256 + c0] = oB;
    }
  }
}

// ---------------------------------------------------------------------------
// Persistent fused sampler, 3 CTAs/SM (reg cap 85, smem 56.9KB).
// Single h buffer (mid-phase-2 barrier back; hidden by 24 warps/SM).
// Phase 3 writes next step's A-fragments directly (D->A identity).
// smem: actHi 0..8K, h 8..40K, Xbuf 40K..56.9K
// ---------------------------------------------------------------------------
#define XSTRIDE 66

__global__ void __launch_bounds__(256, 3)
persist_sde(const float* __restrict__ X0g, float* __restrict__ out,
            const float* __restrict__ w1s,
            const float* __restrict__ b2, const float* __restrict__ b3) {
  extern __shared__ char sm[];
  char*  actHi = sm;
  char*  hbuf  = sm + 8192;
  float* Xbuf  = (float*)(sm + 40960);

  const int tid  = threadIdx.x;
  const int wid  = tid >> 5;
  const int lane = tid & 31;
  const int g    = lane >> 2;
  const int t    = lane & 3;
  const int sample  = blockIdx.x >> 10;
  const int rowBase = (blockIdx.x & 1023) * 64;
  float* outp = out + (size_t)sample * NELEM;

  uint32_t sk[2][2];
  dev_split2(0u, 1u, sk);
  uint32_t ks[2][2];
  dev_split2(sk[sample][0], sk[sample][1], ks);
  uint32_t ke0 = ks[0][0], ke1 = ks[0][1];
  uint32_t kl0 = ks[1][0], kl1 = ks[1][1];

  const int mrow = wid >> 2, ncol = wid & 3;     // 2x4 warp grid (GEMM1/2)
  const int mrow3 = wid >> 1, ncol3 = wid & 1;   // 4x2 warp grid (GEMM3)

#pragma unroll 1
  for (int n = 0; n < 64; ++n) {
    const float s = (float)n * 0.015625f;
    float cf = 0.0f;
    uint32_t nk0, nk1;
    if (n == 0) {
      nk0 = ke0; nk1 = ke1;
      // ---- one-time stage of X0 hi-frags ----
#pragma unroll
      for (int it = 0; it < 2; ++it) {
        int tile = wid * 2 + it;
        int mi = tile >> 2, ki = tile & 3;
        int kc = ki * 16;
        const float* p0 = X0g + (size_t)(rowBase + mi * 16 + g) * DIM + kc;
        const float* p1 = p0 + 8 * DIM;
        float2 v00 = *(const float2*)(p0 + 2 * t);
        float2 v01 = *(const float2*)(p0 + 2 * t + 8);
        float2 v10 = *(const float2*)(p1 + 2 * t);
        float2 v11 = *(const float2*)(p1 + 2 * t + 8);
        uint32_t h0 = pack_h2(v00.x, v00.y);
        uint32_t h1 = pack_h2(v10.x, v10.y);
        uint32_t h2 = pack_h2(v01.x, v01.y);
        uint32_t h3 = pack_h2(v11.x, v11.y);
        int off = (mi * 4 + ki) * 512 + lane * 16;
        *(uint4*)(actHi + off) = make_uint4(h0, h1, h2, h3);
      }
      __syncthreads();
    } else {
      uint32_t kk[2][2];
      dev_split2(kl0, kl1, kk);
      kl0 = kk[0][0]; kl1 = kk[0][1];
      nk0 = kk[1][0]; nk1 = kk[1][1];
      const float sg = 1.0f - s;
      cf = 0.5f * (1.0f - sg * sg) / (s * sg);
    }

    // ---- phase 1: h1 = relu(P0 + Xin @ W1a + s*w1s) -> hbuf ----
    {
      float acc[2][8][4];
#pragma unroll
      for (int j = 0; j < 8; ++j) {
        int c0 = (ncol * 8 + j) * 8 + 2 * t;
#pragma unroll
        for (int mt = 0; mt < 2; ++mt) {
          int r = rowBase + (mrow * 2 + mt) * 16 + g;
          float2 pA = *(const float2*)&g_p0[(size_t)r * 256 + c0];
          float2 pB = *(const float2*)&g_p0[(size_t)(r + 8) * 256 + c0];
          acc[mt][j][0] = pA.x; acc[mt][j][1] = pA.y;
          acc[mt][j][2] = pB.x; acc[mt][j][3] = pB.y;
        }
      }
      gemm1p<4, 8, 2>(acc, actHi, mrow * 2, lane, g_w1af, ncol * 8);
#pragma unroll
      for (int j = 0; j < 8; ++j) {
        int nj = ncol * 8 + j;
        int c0 = nj * 8 + 2 * t;
        float bb0 = s * w1s[c0];
        float bb1 = s * w1s[c0 + 1];
#pragma unroll
        for (int mt = 0; mt < 2; ++mt) {
          int mi = mrow * 2 + mt;
          float v00 = fmaxf(acc[mt][j][0] + bb0, 0.f);
          float v01 = fmaxf(acc[mt][j][1] + bb1, 0.f);
          float v10 = fmaxf(acc[mt][j][2] + bb0, 0.f);
          float v11 = fmaxf(acc[mt][j][3] + bb1, 0.f);
          uint32_t h0 = pack_h2(v00, v01);
          uint32_t h1 = pack_h2(v10, v11);
          int off = (mi * 16 + (nj >> 1)) * 512 + lane * 16 + (nj & 1) * 8;
          *(uint2*)(hbuf + off) = make_uint2(h0, h1);
        }
      }
    }
    __syncthreads();

    // ---- phase 2: h2 = relu(h1 @ W2 + b2), overwrite hbuf after barrier ----
    {
      float acc[2][8][4];
#pragma unroll
      for (int a = 0; a < 2; ++a)
#pragma unroll
        for (int b = 0; b < 8; ++b)
#pragma unroll
          for (int c = 0; c < 4; ++c) acc[a][b][c] = 0.f;
      gemm1p<16, 8, 2>(acc, hbuf, mrow * 2, lane, g_w2f, ncol * 8);
      __syncthreads();   // all warps done reading h1 before overwrite
#pragma unroll
      for (int j = 0; j < 8; ++j) {
        int nj = ncol * 8 + j;
        int c0 = nj * 8 + 2 * t;
        float bb0 = b2[c0];
        float bb1 = b2[c0 + 1];
#pragma unroll
        for (int mt = 0; mt < 2; ++mt) {
          int mi = mrow * 2 + mt;
          float v00 = fmaxf(acc[mt][j][0] + bb0, 0.f);
          float v01 = fmaxf(acc[mt][j][1] + bb1, 0.f);
          float v10 = fmaxf(acc[mt][j][2] + bb0, 0.f);
          float v11 = fmaxf(acc[mt][j][3] + bb1, 0.f);
          uint32_t h0 = pack_h2(v00, v01);
          uint32_t h1 = pack_h2(v10, v11);
          int off = (mi * 16 + (nj >> 1)) * 512 + lane * 16 + (nj & 1) * 8;
          *(uint2*)(hbuf + off) = make_uint2(h0, h1);
        }
      }
    }
    __syncthreads();

    // ---- phase 3: bd = h2 @ W3 + b3; SDE update + threefry;
    //      write Xbuf (f32 carry) AND next step's A-frags directly ----
    {
      float acc[1][4][4];
#pragma unroll
      for (int b = 0; b < 4; ++b)
#pragma unroll
        for (int c = 0; c < 4; ++c) acc[0][b][c] = 0.f;
      gemm1p<16, 4, 1>(acc, hbuf, mrow3, lane, g_w3f, ncol3 * 4);
#pragma unroll
      for (int j = 0; j < 4; ++j) {
        int nj = ncol3 * 4 + j;
        int c0 = nj * 8 + 2 * t;
        float bb0 = b3[c0], bb1 = b3[c0 + 1];
        float ox[2], oy[2];
#pragma unroll
        for (int half = 0; half < 2; ++half) {
          int rl = mrow3 * 16 + g + half * 8;
          int r  = rowBase + rl;
          float bA = acc[0][j][half * 2 + 0] + bb0;
          float bB = acc[0][j][half * 2 + 1] + bb1;
          int i0 = r * DIM + c0;
          float2 x0v = *(const float2*)(X0g + i0);
          float2 Xo;
          if (n == 0) Xo = x0v;
          else        Xo = *(const float2*)&Xbuf[rl * XSTRIDE + c0];
          uint32_t u0 = 0u, u1 = (uint32_t)i0;
          tf2x32(nk0, nk1, u0, u1);
          float e0 = bits_to_normal(u0 ^ u1);
          uint32_t w0 = 0u, w1 = (uint32_t)(i0 + 1);
          tf2x32(nk0, nk1, w0, w1);
          float e1 = bits_to_normal(w0 ^ w1);
          float d0 = bA + cf * (s * bA - Xo.x + x0v.x);
          float d1 = bB + cf * (s * bB - Xo.y + x0v.y);
          float2 o;
          o.x = Xo.x + 0.015625f * d0 + 0.125f * e0;
          o.y = Xo.y + 0.015625f * d1 + 0.125f * e1;
          *(float2*)&Xbuf[rl * XSTRIDE + c0] = o;
          if (n == 63) *(float2*)(outp + i0) = o;
          ox[half] = o.x; oy[half] = o.y;
        }
        // D-frag -> A-frag identity: tile (mi=mrow3, ki=nj>>1)
        int off = (mrow3 * 4 + (nj >> 1)) * 512 + lane * 16 + (nj & 1) * 8;
        *(uint2*)(actHi + off) =
            make_uint2(pack_h2(ox[0], oy[0]), pack_h2(ox[1], oy[1]));
      }
    }
    __syncthreads();   // actHi/Xbuf ready for next step
  }
}

// ---------------------------------------------------------------------------
// Host
// ---------------------------------------------------------------------------
extern "C" void kernel_launch(void* const* d_in, const int* in_sizes, int n_in,
                              void* d_out, int out_size) {
  (void)in_sizes; (void)n_in; (void)out_size;
  const float* X0 = (const float*)d_in[0];
  const float* W1 = (const float*)d_in[1];   // [129, 256]
  const float* b1 = (const float*)d_in[2];
  const float* W2 = (const float*)d_in[3];   // [256, 256]
  const float* b2 = (const float*)d_in[4];
  const float* W3 = (const float*)d_in[5];   // [256, 64]
  const float* b3 = (const float*)d_in[6];
  float* out = (float*)d_out;                // [2, 65536, 64]

  const float* w1s = W1 + 128 * 256;         // s-feature row

  constexpr int SMEM_P0 = 16384;
  constexpr int SMEM = 40960 + 64 * XSTRIDE * 4;   // 57856 B -> 3 CTAs/SM
  cudaFuncSetAttribute((const void*)persist_sde,
                       cudaFuncAttributeMaxDynamicSharedMemorySize, SMEM);

  prep_weights<<<112, 256>>>(W1, W2, W3);
  prep_p0<<<1024, 256, SMEM_P0>>>(X0, b1);
  persist_sde<<<2048, 256, SMEM>>>(X0, out, w1s, b2, b3);
}